// round 9
// baseline (speedup 1.0000x reference)
#include <cuda_runtime.h>
#include <math.h>
#include <stdint.h>

// Problem constants
#define BB 16
#define MM 128
#define LL 32
#define SS 512
#define DD 768
#define HH 12
#define HD 64
#define DFF 3072
#define NL 4
#define NE 50000
#define NROWS (BB*MM)          // 2048
#define KPAD 128               // padded K for classifier stage 2

// ---------------- scratch (static device globals; no allocation) ----------------
__device__ __align__(16) float g_x[NROWS*DD];
__device__ __align__(16) float g_qkv[NROWS*3*DD];
__device__ __align__(16) float g_attnout[NROWS*DD];
__device__ __align__(16) float g_branch[NROWS*DD];
__device__ __align__(16) float g_ffh[NROWS*DFF];
__device__ __align__(16) float g_probs[BB*HH*MM*MM];
__device__ __align__(16) float g_tpad[NROWS*KPAD];
__device__ __align__(16) float g_w2pad[NE*KPAD];
__device__ __align__(16) float g_dl[BB*LL];

// ---------------- block reduction helper ----------------
__device__ __forceinline__ float block_reduce_sum(float v) {
    __shared__ float red[8];
    int lane = threadIdx.x & 31, wid = threadIdx.x >> 5, nw = (int)(blockDim.x >> 5);
    #pragma unroll
    for (int o = 16; o > 0; o >>= 1) v += __shfl_down_sync(0xffffffffu, v, o);
    __syncthreads();
    if (lane == 0) red[wid] = v;
    __syncthreads();
    float s = 0.f;
    for (int i = 0; i < nw; i++) s += red[i];
    return s;
}

// ---------------- mention pooling ----------------
__global__ void dot_kernel(const float* __restrict__ lhs, const float* __restrict__ aw,
                           float* __restrict__ dl) {
    int bl = blockIdx.x;                 // b*32 + l
    int b = bl >> 5, l = bl & 31;
    const float* r = lhs + ((size_t)b*SS + l)*DD;
    float s = 0.f;
    for (int d = threadIdx.x; d < DD; d += blockDim.x) s += r[d]*aw[d];
    s = block_reduce_sum(s);
    if (threadIdx.x == 0) dl[bl] = s;
}

// pos/mask are int32 (jax x64 disabled silently downcasts the int64 cast).
__global__ void pool_kernel(const float* __restrict__ lhs,
                            const int* __restrict__ pos,
                            const int* __restrict__ mask,
                            const float* __restrict__ dl,
                            const float* __restrict__ attn_b,
                            float* __restrict__ x) {
    int bm = blockIdx.x;                 // b*128 + m
    int b = bm >> 7;
    __shared__ float p[LL];
    __shared__ int s_vlen;
    if (threadIdx.x == 0) {
        int vlen = 0;
        if (mask[bm] != 0) {
            const int* pr = pos + (size_t)bm*LL;
            while (vlen < LL && pr[vlen] != -1) vlen++;
        }
        s_vlen = vlen;
        float ab = attn_b[0];
        float lg[LL];
        float mx = -INFINITY;
        for (int l = 0; l < LL; l++) {
            lg[l] = (l < vlen ? dl[b*LL + l] : 0.f) + ab;
            mx = fmaxf(mx, lg[l]);
        }
        float sum = 0.f;
        for (int l = 0; l < LL; l++) { float e = expf(lg[l]-mx); p[l] = e; sum += e; }
        float inv = 1.f/sum;
        for (int l = 0; l < LL; l++) p[l] *= inv;
    }
    __syncthreads();
    int vlen = s_vlen;
    float* xr = x + (size_t)bm*DD;
    for (int d = threadIdx.x; d < DD; d += blockDim.x) {
        float acc = 0.f;
        for (int l = 0; l < vlen; l++)
            acc += p[l] * lhs[((size_t)b*SS + l)*DD + d];
        xr[d] = acc;
    }
}

// ---------------- tf32 tensor-core GEMM, warp tile 64x64 ----------------
// C[M,N] = A[M,K]*B[N,K]^T (+bias)(+relu), fp32 accumulate via
// mma.sync.aligned.m16n8k8.row.col.f32.tf32.tf32.f32.
// 128x128 block tile, 128 threads = 4 warps (2m x 2n), warp tile 64x64
// (4 m-frags x 8 n-frags -> 1.0 LDS words/lane/MMA vs 1.5 at 64x32).
// BK=16 double-buffered; half-tile prefetch interleaved between the two
// k8 compute steps to bound register pressure.
// M mult of 128, K mult of 16, lda/ldb mult of 4. Zeros for N <= n < Npad.

__device__ __forceinline__ uint32_t f2tf32(float x) {
    uint32_t y;
    asm("cvt.rna.tf32.f32 %0, %1;" : "=r"(y) : "f"(x));
    return y;
}

__device__ __forceinline__ void mma_tf32(float* c, const uint32_t* a, const uint32_t* b) {
    asm volatile(
        "mma.sync.aligned.m16n8k8.row.col.f32.tf32.tf32.f32 "
        "{%0,%1,%2,%3}, {%4,%5,%6,%7}, {%8,%9}, {%0,%1,%2,%3};\n"
        : "+f"(c[0]), "+f"(c[1]), "+f"(c[2]), "+f"(c[3])
        : "r"(a[0]), "r"(a[1]), "r"(a[2]), "r"(a[3]), "r"(b[0]), "r"(b[1]));
}

#define SMS 136   // smem row stride in words; 136 % 32 == 8 -> conflict-free

__global__ __launch_bounds__(128, 2)
void tgemm_nt(const float* __restrict__ A, const float* __restrict__ B,
              const float* __restrict__ bias, float* __restrict__ C,
              int M, int N, int K, int lda, int ldb, int ldc, int Npad, int relu) {
    __shared__ uint32_t As[2][16][SMS];   // [buf][k][m]
    __shared__ uint32_t Bs[2][16][SMS];   // [buf][k][n]
    int t = threadIdx.x;
    int m0 = blockIdx.y * 128;
    int n0 = blockIdx.x * 128;

    // staging: thread t owns row t of both tiles (one row per thread)
    const float* Ap = A + (size_t)(m0 + t)*lda;
    bool bv = (n0 + t) < N;
    const float* Bp = B + (size_t)(n0 + t)*ldb;

    int warp = t >> 5, lane = t & 31;
    int group = lane >> 2, tg = lane & 3;
    int wm = (warp >> 1) * 64;   // 0 / 64
    int wn = (warp & 1) * 64;    // 0 / 64

    float acc[4][8][4];
    #pragma unroll
    for (int mi = 0; mi < 4; mi++)
        #pragma unroll
        for (int ni = 0; ni < 8; ni++)
            #pragma unroll
            for (int r = 0; r < 4; r++) acc[mi][ni][r] = 0.f;

    // stage tile 0 into buffer 0 (both halves)
    #pragma unroll
    for (int h = 0; h < 2; h++) {
        float4 a0 = *(const float4*)(Ap + h*8);
        float4 a1 = *(const float4*)(Ap + h*8 + 4);
        float4 b0 = bv ? *(const float4*)(Bp + h*8)     : make_float4(0.f,0.f,0.f,0.f);
        float4 b1 = bv ? *(const float4*)(Bp + h*8 + 4) : make_float4(0.f,0.f,0.f,0.f);
        As[0][h*8+0][t] = f2tf32(a0.x); As[0][h*8+1][t] = f2tf32(a0.y);
        As[0][h*8+2][t] = f2tf32(a0.z); As[0][h*8+3][t] = f2tf32(a0.w);
        As[0][h*8+4][t] = f2tf32(a1.x); As[0][h*8+5][t] = f2tf32(a1.y);
        As[0][h*8+6][t] = f2tf32(a1.z); As[0][h*8+7][t] = f2tf32(a1.w);
        Bs[0][h*8+0][t] = f2tf32(b0.x); Bs[0][h*8+1][t] = f2tf32(b0.y);
        Bs[0][h*8+2][t] = f2tf32(b0.z); Bs[0][h*8+3][t] = f2tf32(b0.w);
        Bs[0][h*8+4][t] = f2tf32(b1.x); Bs[0][h*8+5][t] = f2tf32(b1.y);
        Bs[0][h*8+6][t] = f2tf32(b1.z); Bs[0][h*8+7][t] = f2tf32(b1.w);
    }
    __syncthreads();

    int NT = K >> 4;
    int cur = 0;
    for (int kt = 0; kt < NT; kt++) {
        bool more = (kt + 1) < NT;
        int kb = (kt + 1) * 16;
        int nxt = cur ^ 1;
        const uint32_t (*Ac)[SMS] = As[cur];
        const uint32_t (*Bc)[SMS] = Bs[cur];
        uint32_t (*An)[SMS] = As[nxt];
        uint32_t (*Bn)[SMS] = Bs[nxt];

        float4 a0, a1, b0, b1;
        if (more) {  // prefetch half 0 of next tile
            a0 = *(const float4*)(Ap + kb);
            a1 = *(const float4*)(Ap + kb + 4);
            b0 = bv ? *(const float4*)(Bp + kb)     : make_float4(0.f,0.f,0.f,0.f);
            b1 = bv ? *(const float4*)(Bp + kb + 4) : make_float4(0.f,0.f,0.f,0.f);
        }

        // ---- compute kk = 0 ----
        {
            uint32_t af[4][4], bf[8][2];
            #pragma unroll
            for (int mi = 0; mi < 4; mi++) {
                int ar = wm + mi*16 + group;
                af[mi][0] = Ac[tg  ][ar];
                af[mi][1] = Ac[tg  ][ar+8];
                af[mi][2] = Ac[tg+4][ar];
                af[mi][3] = Ac[tg+4][ar+8];
            }
            #pragma unroll
            for (int ni = 0; ni < 8; ni++) {
                int bc = wn + ni*8 + group;
                bf[ni][0] = Bc[tg  ][bc];
                bf[ni][1] = Bc[tg+4][bc];
            }
            #pragma unroll
            for (int mi = 0; mi < 4; mi++)
                #pragma unroll
                for (int ni = 0; ni < 8; ni++)
                    mma_tf32(acc[mi][ni], af[mi], bf[ni]);
        }

        if (more) {  // stage half 0, prefetch half 1
            An[0][t] = f2tf32(a0.x); An[1][t] = f2tf32(a0.y);
            An[2][t] = f2tf32(a0.z); An[3][t] = f2tf32(a0.w);
            An[4][t] = f2tf32(a1.x); An[5][t] = f2tf32(a1.y);
            An[6][t] = f2tf32(a1.z); An[7][t] = f2tf32(a1.w);
            Bn[0][t] = f2tf32(b0.x); Bn[1][t] = f2tf32(b0.y);
            Bn[2][t] = f2tf32(b0.z); Bn[3][t] = f2tf32(b0.w);
            Bn[4][t] = f2tf32(b1.x); Bn[5][t] = f2tf32(b1.y);
            Bn[6][t] = f2tf32(b1.z); Bn[7][t] = f2tf32(b1.w);
            a0 = *(const float4*)(Ap + kb + 8);
            a1 = *(const float4*)(Ap + kb + 12);
            b0 = bv ? *(const float4*)(Bp + kb + 8)  : make_float4(0.f,0.f,0.f,0.f);
            b1 = bv ? *(const float4*)(Bp + kb + 12) : make_float4(0.f,0.f,0.f,0.f);
        }

        // ---- compute kk = 8 ----
        {
            uint32_t af[4][4], bf[8][2];
            #pragma unroll
            for (int mi = 0; mi < 4; mi++) {
                int ar = wm + mi*16 + group;
                af[mi][0] = Ac[8+tg  ][ar];
                af[mi][1] = Ac[8+tg  ][ar+8];
                af[mi][2] = Ac[8+tg+4][ar];
                af[mi][3] = Ac[8+tg+4][ar+8];
            }
            #pragma unroll
            for (int ni = 0; ni < 8; ni++) {
                int bc = wn + ni*8 + group;
                bf[ni][0] = Bc[8+tg  ][bc];
                bf[ni][1] = Bc[8+tg+4][bc];
            }
            #pragma unroll
            for (int mi = 0; mi < 4; mi++)
                #pragma unroll
                for (int ni = 0; ni < 8; ni++)
                    mma_tf32(acc[mi][ni], af[mi], bf[ni]);
        }

        if (more) {  // stage half 1, flip
            An[ 8][t] = f2tf32(a0.x); An[ 9][t] = f2tf32(a0.y);
            An[10][t] = f2tf32(a0.z); An[11][t] = f2tf32(a0.w);
            An[12][t] = f2tf32(a1.x); An[13][t] = f2tf32(a1.y);
            An[14][t] = f2tf32(a1.z); An[15][t] = f2tf32(a1.w);
            Bn[ 8][t] = f2tf32(b0.x); Bn[ 9][t] = f2tf32(b0.y);
            Bn[10][t] = f2tf32(b0.z); Bn[11][t] = f2tf32(b0.w);
            Bn[12][t] = f2tf32(b1.x); Bn[13][t] = f2tf32(b1.y);
            Bn[14][t] = f2tf32(b1.z); Bn[15][t] = f2tf32(b1.w);
            __syncthreads();
            cur = nxt;
        }
    }

    // epilogue: c0:(g, 2tg) c1:(g, 2tg+1) c2:(g+8, 2tg) c3:(g+8, 2tg+1)
    #pragma unroll
    for (int mi = 0; mi < 4; mi++) {
        int gr0 = m0 + wm + mi*16 + group;
        #pragma unroll
        for (int ni = 0; ni < 8; ni++) {
            int gc = n0 + wn + ni*8 + tg*2;
            #pragma unroll
            for (int half = 0; half < 2; half++) {
                int gm = gr0 + half*8;
                if (gc + 1 < N) {
                    float v0 = acc[mi][ni][half*2+0] + (bias ? bias[gc]   : 0.f);
                    float v1 = acc[mi][ni][half*2+1] + (bias ? bias[gc+1] : 0.f);
                    if (relu) { v0 = fmaxf(v0, 0.f); v1 = fmaxf(v1, 0.f); }
                    *(float2*)&C[(size_t)gm*ldc + gc] = make_float2(v0, v1);
                } else {
                    #pragma unroll
                    for (int j = 0; j < 2; j++) {
                        int gn = gc + j;
                        if (gn < Npad) {
                            float v = 0.f;
                            if (gn < N) {
                                v = acc[mi][ni][half*2 + j] + (bias ? bias[gn] : 0.f);
                                if (relu) v = fmaxf(v, 0.f);
                            }
                            C[(size_t)gm*ldc + gn] = v;
                        }
                    }
                }
            }
        }
    }
}

// ---------------- attention (one block per (b,h), 128 threads = 128 queries) ----------------
__global__ __launch_bounds__(128)
void attn_kernel(const float* __restrict__ qkv, float* __restrict__ probs,
                 float* __restrict__ attnout) {
    __shared__ float Ks[128][64];
    int bh = blockIdx.x;
    int b = bh / HH, h = bh % HH;
    int t = threadIdx.x;
    const float* base = qkv + (size_t)b*MM*(3*DD);
    for (int idx = t; idx < 128*64; idx += 128) {
        int j = idx >> 6, d = idx & 63;
        Ks[j][d] = base[(size_t)j*(3*DD) + DD + h*HD + d];
    }
    __syncthreads();
    float q[64];
    const float* qrow = base + (size_t)t*(3*DD) + h*HD;
    #pragma unroll
    for (int d0 = 0; d0 < 64; d0 += 4) {
        float4 v = *(const float4*)(qrow + d0);
        q[d0] = v.x; q[d0+1] = v.y; q[d0+2] = v.z; q[d0+3] = v.w;
    }
    float mx = -INFINITY;
    float* prow = probs + (size_t)bh*MM*MM;
    const float scale = 0.125f;
    for (int j = 0; j < 128; j++) {
        float s = 0.f;
        #pragma unroll
        for (int d = 0; d < 64; d++) s += q[d]*Ks[j][d];
        s *= scale;
        mx = fmaxf(mx, s);
        prow[(size_t)j*128 + t] = s;
    }
    __syncthreads();
    for (int idx = t; idx < 128*64; idx += 128) {
        int j = idx >> 6, d = idx & 63;
        Ks[j][d] = base[(size_t)j*(3*DD) + 2*DD + h*HD + d];
    }
    __syncthreads();
    float acc[64];
    #pragma unroll
    for (int d = 0; d < 64; d++) acc[d] = 0.f;
    float sum = 0.f;
    for (int j = 0; j < 128; j++) {
        float p = expf(prow[(size_t)j*128 + t] - mx);
        sum += p;
        #pragma unroll
        for (int d = 0; d < 64; d++) acc[d] += p*Ks[j][d];
    }
    float inv = 1.f/sum;
    float* orow = attnout + (size_t)(b*MM + t)*DD + h*HD;
    #pragma unroll
    for (int d = 0; d < 64; d++) orow[d] = acc[d]*inv;
}

// ---------------- fused residual + layernorm (in-place into x) ----------------
__global__ void add_ln_kernel(float* __restrict__ x, const float* __restrict__ y,
                              const float* __restrict__ w, const float* __restrict__ b) {
    __shared__ float buf[DD];
    int row = blockIdx.x, t = threadIdx.x;
    float* xr = x + (size_t)row*DD;
    const float* yr = y + (size_t)row*DD;
    float ls = 0.f;
    for (int d = t; d < DD; d += blockDim.x) {
        float v = xr[d] + yr[d];
        buf[d] = v;
        ls += v;
    }
    float mean = block_reduce_sum(ls) * (1.f/DD);
    float lv = 0.f;
    for (int d = t; d < DD; d += blockDim.x) {
        float c = buf[d] - mean;
        lv += c*c;
    }
    float var = block_reduce_sum(lv) * (1.f/DD);
    float r = rsqrtf(var + 1e-5f);
    for (int d = t; d < DD; d += blockDim.x)
        xr[d] = (buf[d] - mean)*r*w[d] + b[d];
}

// ---------------- pad cls_w2 [NE,100] -> [NE,128] ----------------
__global__ void pad_w2_kernel(const float* __restrict__ w2, float* __restrict__ w2p) {
    size_t i = (size_t)blockIdx.x*blockDim.x + threadIdx.x;
    if (i < (size_t)NE*KPAD) {
        int r = (int)(i >> 7), c = (int)(i & 127);
        w2p[i] = (c < 100) ? w2[(size_t)r*100 + c] : 0.f;
    }
}

// ---------------- launch ----------------
extern "C" void kernel_launch(void* const* d_in, const int* in_sizes, int n_in,
                              void* d_out, int out_size) {
    (void)in_sizes; (void)n_in; (void)out_size;
    const float* lhs    = (const float*)d_in[0];
    const int*   pos    = (const int*)d_in[1];     // int32
    const int*   mask   = (const int*)d_in[2];     // int32
    const float* attn_w = (const float*)d_in[3];
    const float* attn_b = (const float*)d_in[4];
    const float* qkv_w  = (const float*)d_in[5];
    const float* qkv_b  = (const float*)d_in[6];
    const float* out_w  = (const float*)d_in[7];
    const float* out_b  = (const float*)d_in[8];
    const float* ln1_w  = (const float*)d_in[9];
    const float* ln1_b  = (const float*)d_in[10];
    const float* ff1_w  = (const float*)d_in[11];
    const float* ff1_b  = (const float*)d_in[12];
    const float* ff2_w  = (const float*)d_in[13];
    const float* ff2_b  = (const float*)d_in[14];
    const float* ln2_w  = (const float*)d_in[15];
    const float* ln2_b  = (const float*)d_in[16];
    const float* cls_w1 = (const float*)d_in[17];
    const float* cls_w2 = (const float*)d_in[18];
    const float* cls_b2 = (const float*)d_in[19];
    float* out = (float*)d_out;

    float *x, *qkv, *attnout, *branch, *ffh, *probs, *tpad, *w2pad, *dl;
    cudaGetSymbolAddress((void**)&x,       g_x);
    cudaGetSymbolAddress((void**)&qkv,     g_qkv);
    cudaGetSymbolAddress((void**)&attnout, g_attnout);
    cudaGetSymbolAddress((void**)&branch,  g_branch);
    cudaGetSymbolAddress((void**)&ffh,     g_ffh);
    cudaGetSymbolAddress((void**)&probs,   g_probs);
    cudaGetSymbolAddress((void**)&tpad,    g_tpad);
    cudaGetSymbolAddress((void**)&w2pad,   g_w2pad);
    cudaGetSymbolAddress((void**)&dl,      g_dl);

    pad_w2_kernel<<<(NE*KPAD + 255)/256, 256>>>(cls_w2, w2pad);

    dot_kernel<<<BB*LL, 128>>>(lhs, attn_w, dl);
    pool_kernel<<<NROWS, 256>>>(lhs, pos, mask, dl, attn_b, x);

    for (int i = 0; i < NL; i++) {
        tgemm_nt<<<dim3(18,16), 128>>>(x, qkv_w + (size_t)i*3*DD*DD, qkv_b + (size_t)i*3*DD,
                                       qkv, NROWS, 3*DD, DD, DD, DD, 3*DD, 3*DD, 0);
        attn_kernel<<<BB*HH, 128>>>(qkv, probs, attnout);
        tgemm_nt<<<dim3(6,16), 128>>>(attnout, out_w + (size_t)i*DD*DD, out_b + (size_t)i*DD,
                                      branch, NROWS, DD, DD, DD, DD, DD, DD, 0);
        add_ln_kernel<<<NROWS, 256>>>(x, branch, ln1_w + (size_t)i*DD, ln1_b + (size_t)i*DD);
        tgemm_nt<<<dim3(24,16), 128>>>(x, ff1_w + (size_t)i*DFF*DD, ff1_b + (size_t)i*DFF,
                                       ffh, NROWS, DFF, DD, DD, DD, DFF, DFF, 1);
        tgemm_nt<<<dim3(6,16), 128>>>(ffh, ff2_w + (size_t)i*DD*DFF, ff2_b + (size_t)i*DD,
                                      branch, NROWS, DD, DFF, DFF, DFF, DD, DD, 0);
        add_ln_kernel<<<NROWS, 256>>>(x, branch, ln2_w + (size_t)i*DD, ln2_b + (size_t)i*DD);
    }

    tgemm_nt<<<dim3(1,16), 128>>>(x, cls_w1, (const float*)nullptr, tpad,
                                  NROWS, 100, DD, DD, DD, KPAD, KPAD, 0);
    tgemm_nt<<<dim3((NE + 127)/128, 16), 128>>>(tpad, w2pad, cls_b2, out,
                                                NROWS, NE, KPAD, KPAD, KPAD, NE, NE, 0);
}

// round 12
// speedup vs baseline: 1.0652x; 1.0652x over previous
#include <cuda_runtime.h>
#include <math.h>
#include <stdint.h>

// Problem constants
#define BB 16
#define MM 128
#define LL 32
#define SS 512
#define DD 768
#define HH 12
#define HD 64
#define DFF 3072
#define NL 4
#define NE 50000
#define NROWS (BB*MM)          // 2048
#define KPAD 128               // padded K for classifier stage 2

// ---------------- scratch (static device globals; no allocation) ----------------
__device__ __align__(16) float g_x[NROWS*DD];
__device__ __align__(16) float g_qkv[NROWS*3*DD];
__device__ __align__(16) float g_attnout[NROWS*DD];
__device__ __align__(16) float g_branch[NROWS*DD];
__device__ __align__(16) float g_ffh[NROWS*DFF];
__device__ __align__(16) float g_probs[BB*HH*MM*MM];
__device__ __align__(16) float g_tpad[NROWS*KPAD];
__device__ __align__(16) float g_w2pad[NE*KPAD];
__device__ __align__(16) float g_dl[BB*LL];

// ---------------- block reduction helper ----------------
__device__ __forceinline__ float block_reduce_sum(float v) {
    __shared__ float red[8];
    int lane = threadIdx.x & 31, wid = threadIdx.x >> 5, nw = (int)(blockDim.x >> 5);
    #pragma unroll
    for (int o = 16; o > 0; o >>= 1) v += __shfl_down_sync(0xffffffffu, v, o);
    __syncthreads();
    if (lane == 0) red[wid] = v;
    __syncthreads();
    float s = 0.f;
    for (int i = 0; i < nw; i++) s += red[i];
    return s;
}

// ---------------- mention pooling ----------------
__global__ void dot_kernel(const float* __restrict__ lhs, const float* __restrict__ aw,
                           float* __restrict__ dl) {
    int bl = blockIdx.x;                 // b*32 + l
    int b = bl >> 5, l = bl & 31;
    const float* r = lhs + ((size_t)b*SS + l)*DD;
    float s = 0.f;
    for (int d = threadIdx.x; d < DD; d += blockDim.x) s += r[d]*aw[d];
    s = block_reduce_sum(s);
    if (threadIdx.x == 0) dl[bl] = s;
}

// pos/mask are int32 (jax x64 disabled silently downcasts the int64 cast).
__global__ void pool_kernel(const float* __restrict__ lhs,
                            const int* __restrict__ pos,
                            const int* __restrict__ mask,
                            const float* __restrict__ dl,
                            const float* __restrict__ attn_b,
                            float* __restrict__ x) {
    int bm = blockIdx.x;                 // b*128 + m
    int b = bm >> 7;
    __shared__ float p[LL];
    __shared__ int s_vlen;
    if (threadIdx.x == 0) {
        int vlen = 0;
        if (mask[bm] != 0) {
            const int* pr = pos + (size_t)bm*LL;
            while (vlen < LL && pr[vlen] != -1) vlen++;
        }
        s_vlen = vlen;
        float ab = attn_b[0];
        float lg[LL];
        float mx = -INFINITY;
        for (int l = 0; l < LL; l++) {
            lg[l] = (l < vlen ? dl[b*LL + l] : 0.f) + ab;
            mx = fmaxf(mx, lg[l]);
        }
        float sum = 0.f;
        for (int l = 0; l < LL; l++) { float e = expf(lg[l]-mx); p[l] = e; sum += e; }
        float inv = 1.f/sum;
        for (int l = 0; l < LL; l++) p[l] *= inv;
    }
    __syncthreads();
    int vlen = s_vlen;
    float* xr = x + (size_t)bm*DD;
    for (int d = threadIdx.x; d < DD; d += blockDim.x) {
        float acc = 0.f;
        for (int l = 0; l < vlen; l++)
            acc += p[l] * lhs[((size_t)b*SS + l)*DD + d];
        xr[d] = acc;
    }
}

// ---------------- shared tf32 helpers ----------------
__device__ __forceinline__ uint32_t f2tf32(float x) {
    uint32_t y;
    asm("cvt.rna.tf32.f32 %0, %1;" : "=r"(y) : "f"(x));
    return y;
}

__device__ __forceinline__ void mma_tf32(float* c, const uint32_t* a, const uint32_t* b) {
    asm volatile(
        "mma.sync.aligned.m16n8k8.row.col.f32.tf32.tf32.f32 "
        "{%0,%1,%2,%3}, {%4,%5,%6,%7}, {%8,%9}, {%0,%1,%2,%3};\n"
        : "+f"(c[0]), "+f"(c[1]), "+f"(c[2]), "+f"(c[3])
        : "r"(a[0]), "r"(a[1]), "r"(a[2]), "r"(a[3]), "r"(b[0]), "r"(b[1]));
}

#define SMS  136   // 128 + 8 pad; 136 % 32 == 8 -> conflict-free
#define SMSA 264   // 256 + 8 pad; 264 % 32 == 8 -> conflict-free

// ============ tgemm_big: 256x128 block tile, 8 warps (4m x 2n), warp 64x64 ============
// C[M,N] = A[M,K]*B[N,K]^T (+bias)(+relu). M mult of 256, K mult of 32.
__global__ __launch_bounds__(256)
void tgemm_big(const float* __restrict__ A, const float* __restrict__ B,
               const float* __restrict__ bias, float* __restrict__ C,
               int M, int N, int K, int lda, int ldb, int ldc, int relu) {
    __shared__ uint32_t As[2][16][SMSA];   // [buf][k][m 0..255]
    __shared__ uint32_t Bs[2][16][SMS];    // [buf][k][n 0..127]
    int t = threadIdx.x;
    int m0 = blockIdx.y * 256;
    int n0 = blockIdx.x * 128;

    // A staging: thread t owns row t (16 k-values). B: row t>>1, k-half (t&1)*8.
    const float* Ap = A + (size_t)(m0 + t)*lda;
    int brow = t >> 1, bko = (t & 1)*8;
    bool bv = (n0 + brow) < N;
    const float* Bp = B + (size_t)(n0 + brow)*ldb + bko;

    int warp = t >> 5, lane = t & 31;
    int group = lane >> 2, tg = lane & 3;
    int wm = (warp >> 1) * 64;   // 0,64,128,192
    int wn = (warp & 1) * 64;    // 0,64

    float acc[4][8][4];
    #pragma unroll
    for (int mi = 0; mi < 4; mi++)
        #pragma unroll
        for (int ni = 0; ni < 8; ni++)
            #pragma unroll
            for (int r = 0; r < 4; r++) acc[mi][ni][r] = 0.f;

    // stage tile 0 -> buffer 0
    {
        #pragma unroll
        for (int h = 0; h < 4; h++) {
            float4 a = *(const float4*)(Ap + h*4);
            As[0][h*4+0][t] = f2tf32(a.x); As[0][h*4+1][t] = f2tf32(a.y);
            As[0][h*4+2][t] = f2tf32(a.z); As[0][h*4+3][t] = f2tf32(a.w);
        }
        float4 b0 = bv ? *(const float4*)(Bp)     : make_float4(0.f,0.f,0.f,0.f);
        float4 b1 = bv ? *(const float4*)(Bp + 4) : make_float4(0.f,0.f,0.f,0.f);
        Bs[0][bko+0][brow] = f2tf32(b0.x); Bs[0][bko+1][brow] = f2tf32(b0.y);
        Bs[0][bko+2][brow] = f2tf32(b0.z); Bs[0][bko+3][brow] = f2tf32(b0.w);
        Bs[0][bko+4][brow] = f2tf32(b1.x); Bs[0][bko+5][brow] = f2tf32(b1.y);
        Bs[0][bko+6][brow] = f2tf32(b1.z); Bs[0][bko+7][brow] = f2tf32(b1.w);
    }
    __syncthreads();

    int NT = K >> 4;
    int cur = 0;
    for (int kt = 0; kt < NT; kt++) {
        bool more = (kt + 1) < NT;
        int kb = (kt + 1) * 16;
        int nxt = cur ^ 1;

        float4 pa[4], pb0, pb1;
        if (more) {
            #pragma unroll
            for (int h = 0; h < 4; h++) pa[h] = *(const float4*)(Ap + kb + h*4);
            pb0 = bv ? *(const float4*)(Bp + kb)     : make_float4(0.f,0.f,0.f,0.f);
            pb1 = bv ? *(const float4*)(Bp + kb + 4) : make_float4(0.f,0.f,0.f,0.f);
        }

        #pragma unroll
        for (int kk = 0; kk < 16; kk += 8) {
            uint32_t af[4][4], bf[8][2];
            #pragma unroll
            for (int mi = 0; mi < 4; mi++) {
                int ar = wm + mi*16 + group;
                af[mi][0] = As[cur][kk+tg  ][ar];
                af[mi][1] = As[cur][kk+tg  ][ar+8];
                af[mi][2] = As[cur][kk+tg+4][ar];
                af[mi][3] = As[cur][kk+tg+4][ar+8];
            }
            #pragma unroll
            for (int ni = 0; ni < 8; ni++) {
                int bc = wn + ni*8 + group;
                bf[ni][0] = Bs[cur][kk+tg  ][bc];
                bf[ni][1] = Bs[cur][kk+tg+4][bc];
            }
            #pragma unroll
            for (int mi = 0; mi < 4; mi++)
                #pragma unroll
                for (int ni = 0; ni < 8; ni++)
                    mma_tf32(acc[mi][ni], af[mi], bf[ni]);
        }

        if (more) {
            #pragma unroll
            for (int h = 0; h < 4; h++) {
                As[nxt][h*4+0][t] = f2tf32(pa[h].x); As[nxt][h*4+1][t] = f2tf32(pa[h].y);
                As[nxt][h*4+2][t] = f2tf32(pa[h].z); As[nxt][h*4+3][t] = f2tf32(pa[h].w);
            }
            Bs[nxt][bko+0][brow] = f2tf32(pb0.x); Bs[nxt][bko+1][brow] = f2tf32(pb0.y);
            Bs[nxt][bko+2][brow] = f2tf32(pb0.z); Bs[nxt][bko+3][brow] = f2tf32(pb0.w);
            Bs[nxt][bko+4][brow] = f2tf32(pb1.x); Bs[nxt][bko+5][brow] = f2tf32(pb1.y);
            Bs[nxt][bko+6][brow] = f2tf32(pb1.z); Bs[nxt][bko+7][brow] = f2tf32(pb1.w);
            __syncthreads();
            cur = nxt;
        }
    }

    // epilogue
    #pragma unroll
    for (int mi = 0; mi < 4; mi++) {
        int gr0 = m0 + wm + mi*16 + group;
        #pragma unroll
        for (int ni = 0; ni < 8; ni++) {
            int gc = n0 + wn + ni*8 + tg*2;
            #pragma unroll
            for (int half = 0; half < 2; half++) {
                int gm = gr0 + half*8;
                if (gc + 1 < N) {
                    float v0 = acc[mi][ni][half*2+0] + (bias ? bias[gc]   : 0.f);
                    float v1 = acc[mi][ni][half*2+1] + (bias ? bias[gc+1] : 0.f);
                    if (relu) { v0 = fmaxf(v0, 0.f); v1 = fmaxf(v1, 0.f); }
                    *(float2*)&C[(size_t)gm*ldc + gc] = make_float2(v0, v1);
                } else {
                    #pragma unroll
                    for (int j = 0; j < 2; j++) {
                        int gn = gc + j;
                        if (gn < N) {
                            float v = acc[mi][ni][half*2 + j] + (bias ? bias[gn] : 0.f);
                            if (relu) v = fmaxf(v, 0.f);
                            C[(size_t)gm*ldc + gn] = v;
                        }
                    }
                }
            }
        }
    }
}

// ============ tgemm_nt: 128x128 tile, 8 warps (2m x 4n), warp 64x32 (R6) ============
__global__ __launch_bounds__(256, 2)
void tgemm_nt(const float* __restrict__ A, const float* __restrict__ B,
              const float* __restrict__ bias, float* __restrict__ C,
              int M, int N, int K, int lda, int ldb, int ldc, int Npad, int relu) {
    __shared__ uint32_t As[2][16][SMS];
    __shared__ uint32_t Bs[2][16][SMS];
    int t = threadIdx.x;
    int m0 = blockIdx.y * 128;
    int n0 = blockIdx.x * 128;

    int lr = t & 127;
    int lk = (t >> 7) * 8;
    const float* Aptr = A + (size_t)(m0 + lr)*lda + lk;
    bool bv = (n0 + lr) < N;
    const float* Bptr = B + (size_t)(n0 + lr)*ldb + lk;

    int warp  = t >> 5, lane = t & 31;
    int group = lane >> 2, tg = lane & 3;
    int wm = (warp >> 2) * 64;
    int wn = (warp & 3) * 32;

    float acc[4][4][4];
    #pragma unroll
    for (int mi = 0; mi < 4; mi++)
        #pragma unroll
        for (int ni = 0; ni < 4; ni++)
            #pragma unroll
            for (int r = 0; r < 4; r++) acc[mi][ni][r] = 0.f;

    float4 pa0 = *(const float4*)(Aptr + 0);
    float4 pa1 = *(const float4*)(Aptr + 4);
    float4 pb0 = bv ? *(const float4*)(Bptr + 0) : make_float4(0.f,0.f,0.f,0.f);
    float4 pb1 = bv ? *(const float4*)(Bptr + 4) : make_float4(0.f,0.f,0.f,0.f);
    As[0][lk+0][lr] = f2tf32(pa0.x); As[0][lk+1][lr] = f2tf32(pa0.y);
    As[0][lk+2][lr] = f2tf32(pa0.z); As[0][lk+3][lr] = f2tf32(pa0.w);
    As[0][lk+4][lr] = f2tf32(pa1.x); As[0][lk+5][lr] = f2tf32(pa1.y);
    As[0][lk+6][lr] = f2tf32(pa1.z); As[0][lk+7][lr] = f2tf32(pa1.w);
    Bs[0][lk+0][lr] = f2tf32(pb0.x); Bs[0][lk+1][lr] = f2tf32(pb0.y);
    Bs[0][lk+2][lr] = f2tf32(pb0.z); Bs[0][lk+3][lr] = f2tf32(pb0.w);
    Bs[0][lk+4][lr] = f2tf32(pb1.x); Bs[0][lk+5][lr] = f2tf32(pb1.y);
    Bs[0][lk+6][lr] = f2tf32(pb1.z); Bs[0][lk+7][lr] = f2tf32(pb1.w);
    __syncthreads();

    int cur = 0;
    for (int k0 = 16; k0 <= K; k0 += 16) {
        bool more = (k0 < K);
        if (more) {
            pa0 = *(const float4*)(Aptr + k0);
            pa1 = *(const float4*)(Aptr + k0 + 4);
            if (bv) {
                pb0 = *(const float4*)(Bptr + k0);
                pb1 = *(const float4*)(Bptr + k0 + 4);
            }
        }

        #pragma unroll
        for (int kk = 0; kk < 16; kk += 8) {
            uint32_t af[4][4], bf[4][2];
            #pragma unroll
            for (int mi = 0; mi < 4; mi++) {
                int ar = wm + mi*16 + group;
                af[mi][0] = As[cur][kk+tg  ][ar];
                af[mi][1] = As[cur][kk+tg  ][ar+8];
                af[mi][2] = As[cur][kk+tg+4][ar];
                af[mi][3] = As[cur][kk+tg+4][ar+8];
            }
            #pragma unroll
            for (int ni = 0; ni < 4; ni++) {
                int bc = wn + ni*8 + group;
                bf[ni][0] = Bs[cur][kk+tg  ][bc];
                bf[ni][1] = Bs[cur][kk+tg+4][bc];
            }
            #pragma unroll
            for (int mi = 0; mi < 4; mi++)
                #pragma unroll
                for (int ni = 0; ni < 4; ni++)
                    mma_tf32(acc[mi][ni], af[mi], bf[ni]);
        }

        if (more) {
            int nxt = cur ^ 1;
            As[nxt][lk+0][lr] = f2tf32(pa0.x); As[nxt][lk+1][lr] = f2tf32(pa0.y);
            As[nxt][lk+2][lr] = f2tf32(pa0.z); As[nxt][lk+3][lr] = f2tf32(pa0.w);
            As[nxt][lk+4][lr] = f2tf32(pa1.x); As[nxt][lk+5][lr] = f2tf32(pa1.y);
            As[nxt][lk+6][lr] = f2tf32(pa1.z); As[nxt][lk+7][lr] = f2tf32(pa1.w);
            Bs[nxt][lk+0][lr] = f2tf32(pb0.x); Bs[nxt][lk+1][lr] = f2tf32(pb0.y);
            Bs[nxt][lk+2][lr] = f2tf32(pb0.z); Bs[nxt][lk+3][lr] = f2tf32(pb0.w);
            Bs[nxt][lk+4][lr] = f2tf32(pb1.x); Bs[nxt][lk+5][lr] = f2tf32(pb1.y);
            Bs[nxt][lk+6][lr] = f2tf32(pb1.z); Bs[nxt][lk+7][lr] = f2tf32(pb1.w);
            __syncthreads();
            cur = nxt;
        }
    }

    #pragma unroll
    for (int mi = 0; mi < 4; mi++) {
        int gr0 = m0 + wm + mi*16 + group;
        #pragma unroll
        for (int ni = 0; ni < 4; ni++) {
            int gc = n0 + wn + ni*8 + tg*2;
            #pragma unroll
            for (int half = 0; half < 2; half++) {
                int gm = gr0 + half*8;
                if (gc + 1 < N) {
                    float v0 = acc[mi][ni][half*2+0] + (bias ? bias[gc]   : 0.f);
                    float v1 = acc[mi][ni][half*2+1] + (bias ? bias[gc+1] : 0.f);
                    if (relu) { v0 = fmaxf(v0, 0.f); v1 = fmaxf(v1, 0.f); }
                    *(float2*)&C[(size_t)gm*ldc + gc] = make_float2(v0, v1);
                } else {
                    #pragma unroll
                    for (int j = 0; j < 2; j++) {
                        int gn = gc + j;
                        if (gn < Npad) {
                            float v = 0.f;
                            if (gn < N) {
                                v = acc[mi][ni][half*2 + j] + (bias ? bias[gn] : 0.f);
                                if (relu) v = fmaxf(v, 0.f);
                            }
                            C[(size_t)gm*ldc + gn] = v;
                        }
                    }
                }
            }
        }
    }
}

// ---------------- attention (one block per (b,h), 128 threads = 128 queries) ----------------
__global__ __launch_bounds__(128)
void attn_kernel(const float* __restrict__ qkv, float* __restrict__ probs,
                 float* __restrict__ attnout) {
    __shared__ float Ks[128][64];
    int bh = blockIdx.x;
    int b = bh / HH, h = bh % HH;
    int t = threadIdx.x;
    const float* base = qkv + (size_t)b*MM*(3*DD);
    for (int idx = t; idx < 128*64; idx += 128) {
        int j = idx >> 6, d = idx & 63;
        Ks[j][d] = base[(size_t)j*(3*DD) + DD + h*HD + d];
    }
    __syncthreads();
    float q[64];
    const float* qrow = base + (size_t)t*(3*DD) + h*HD;
    #pragma unroll
    for (int d0 = 0; d0 < 64; d0 += 4) {
        float4 v = *(const float4*)(qrow + d0);
        q[d0] = v.x; q[d0+1] = v.y; q[d0+2] = v.z; q[d0+3] = v.w;
    }
    float mx = -INFINITY;
    float* prow = probs + (size_t)bh*MM*MM;
    const float scale = 0.125f;
    for (int j = 0; j < 128; j++) {
        float s = 0.f;
        #pragma unroll
        for (int d = 0; d < 64; d++) s += q[d]*Ks[j][d];
        s *= scale;
        mx = fmaxf(mx, s);
        prow[(size_t)j*128 + t] = s;
    }
    __syncthreads();
    for (int idx = t; idx < 128*64; idx += 128) {
        int j = idx >> 6, d = idx & 63;
        Ks[j][d] = base[(size_t)j*(3*DD) + 2*DD + h*HD + d];
    }
    __syncthreads();
    float acc[64];
    #pragma unroll
    for (int d = 0; d < 64; d++) acc[d] = 0.f;
    float sum = 0.f;
    for (int j = 0; j < 128; j++) {
        float p = expf(prow[(size_t)j*128 + t] - mx);
        sum += p;
        #pragma unroll
        for (int d = 0; d < 64; d++) acc[d] += p*Ks[j][d];
    }
    float inv = 1.f/sum;
    float* orow = attnout + (size_t)(b*MM + t)*DD + h*HD;
    #pragma unroll
    for (int d = 0; d < 64; d++) orow[d] = acc[d]*inv;
}

// ---------------- fused residual + layernorm (in-place into x) ----------------
__global__ void add_ln_kernel(float* __restrict__ x, const float* __restrict__ y,
                              const float* __restrict__ w, const float* __restrict__ b) {
    __shared__ float buf[DD];
    int row = blockIdx.x, t = threadIdx.x;
    float* xr = x + (size_t)row*DD;
    const float* yr = y + (size_t)row*DD;
    float ls = 0.f;
    for (int d = t; d < DD; d += blockDim.x) {
        float v = xr[d] + yr[d];
        buf[d] = v;
        ls += v;
    }
    float mean = block_reduce_sum(ls) * (1.f/DD);
    float lv = 0.f;
    for (int d = t; d < DD; d += blockDim.x) {
        float c = buf[d] - mean;
        lv += c*c;
    }
    float var = block_reduce_sum(lv) * (1.f/DD);
    float r = rsqrtf(var + 1e-5f);
    for (int d = t; d < DD; d += blockDim.x)
        xr[d] = (buf[d] - mean)*r*w[d] + b[d];
}

// ---------------- pad cls_w2 [NE,100] -> [NE,128] ----------------
__global__ void pad_w2_kernel(const float* __restrict__ w2, float* __restrict__ w2p) {
    size_t i = (size_t)blockIdx.x*blockDim.x + threadIdx.x;
    if (i < (size_t)NE*KPAD) {
        int r = (int)(i >> 7), c = (int)(i & 127);
        w2p[i] = (c < 100) ? w2[(size_t)r*100 + c] : 0.f;
    }
}

// ---------------- launch ----------------
extern "C" void kernel_launch(void* const* d_in, const int* in_sizes, int n_in,
                              void* d_out, int out_size) {
    (void)in_sizes; (void)n_in; (void)out_size;
    const float* lhs    = (const float*)d_in[0];
    const int*   pos    = (const int*)d_in[1];     // int32
    const int*   mask   = (const int*)d_in[2];     // int32
    const float* attn_w = (const float*)d_in[3];
    const float* attn_b = (const float*)d_in[4];
    const float* qkv_w  = (const float*)d_in[5];
    const float* qkv_b  = (const float*)d_in[6];
    const float* out_w  = (const float*)d_in[7];
    const float* out_b  = (const float*)d_in[8];
    const float* ln1_w  = (const float*)d_in[9];
    const float* ln1_b  = (const float*)d_in[10];
    const float* ff1_w  = (const float*)d_in[11];
    const float* ff1_b  = (const float*)d_in[12];
    const float* ff2_w  = (const float*)d_in[13];
    const float* ff2_b  = (const float*)d_in[14];
    const float* ln2_w  = (const float*)d_in[15];
    const float* ln2_b  = (const float*)d_in[16];
    const float* cls_w1 = (const float*)d_in[17];
    const float* cls_w2 = (const float*)d_in[18];
    const float* cls_b2 = (const float*)d_in[19];
    float* out = (float*)d_out;

    float *x, *qkv, *attnout, *branch, *ffh, *probs, *tpad, *w2pad, *dl;
    cudaGetSymbolAddress((void**)&x,       g_x);
    cudaGetSymbolAddress((void**)&qkv,     g_qkv);
    cudaGetSymbolAddress((void**)&attnout, g_attnout);
    cudaGetSymbolAddress((void**)&branch,  g_branch);
    cudaGetSymbolAddress((void**)&ffh,     g_ffh);
    cudaGetSymbolAddress((void**)&probs,   g_probs);
    cudaGetSymbolAddress((void**)&tpad,    g_tpad);
    cudaGetSymbolAddress((void**)&w2pad,   g_w2pad);
    cudaGetSymbolAddress((void**)&dl,      g_dl);

    pad_w2_kernel<<<(NE*KPAD + 255)/256, 256>>>(cls_w2, w2pad);

    dot_kernel<<<BB*LL, 128>>>(lhs, attn_w, dl);
    pool_kernel<<<NROWS, 256>>>(lhs, pos, mask, dl, attn_b, x);

    for (int i = 0; i < NL; i++) {
        tgemm_big<<<dim3(18,8), 256>>>(x, qkv_w + (size_t)i*3*DD*DD, qkv_b + (size_t)i*3*DD,
                                       qkv, NROWS, 3*DD, DD, DD, DD, 3*DD, 0);
        attn_kernel<<<BB*HH, 128>>>(qkv, probs, attnout);
        tgemm_nt<<<dim3(6,16), 256>>>(attnout, out_w + (size_t)i*DD*DD, out_b + (size_t)i*DD,
                                      branch, NROWS, DD, DD, DD, DD, DD, DD, 0);
        add_ln_kernel<<<NROWS, 256>>>(x, branch, ln1_w + (size_t)i*DD, ln1_b + (size_t)i*DD);
        tgemm_big<<<dim3(24,8), 256>>>(x, ff1_w + (size_t)i*DFF*DD, ff1_b + (size_t)i*DFF,
                                       ffh, NROWS, DFF, DD, DD, DD, DFF, 1);
        tgemm_nt<<<dim3(6,16), 256>>>(ffh, ff2_w + (size_t)i*DD*DFF, ff2_b + (size_t)i*DD,
                                      branch, NROWS, DD, DFF, DFF, DFF, DD, DD, 0);
        add_ln_kernel<<<NROWS, 256>>>(x, branch, ln2_w + (size_t)i*DD, ln2_b + (size_t)i*DD);
    }

    tgemm_nt<<<dim3(1,16), 256>>>(x, cls_w1, (const float*)nullptr, tpad,
                                  NROWS, 100, DD, DD, DD, KPAD, KPAD, 0);
    tgemm_big<<<dim3((NE + 127)/128, 8), 256>>>(tpad, w2pad, cls_b2, out,
                                                NROWS, NE, KPAD, KPAD, KPAD, NE, 0);
}

// round 15
// speedup vs baseline: 1.0977x; 1.0306x over previous
#include <cuda_runtime.h>
#include <math.h>
#include <stdint.h>

// Problem constants
#define BB 16
#define MM 128
#define LL 32
#define SS 512
#define DD 768
#define HH 12
#define HD 64
#define DFF 3072
#define NL 4
#define NE 50000
#define NROWS (BB*MM)          // 2048
#define KPAD 128               // padded K for classifier stage 2

// ---------------- scratch (static device globals; no allocation) ----------------
__device__ __align__(16) float g_x[NROWS*DD];
__device__ __align__(16) float g_qkv[NROWS*3*DD];
__device__ __align__(16) float g_attnout[NROWS*DD];
__device__ __align__(16) float g_branch[NROWS*DD];
__device__ __align__(16) float g_ffh[NROWS*DFF];
__device__ __align__(16) float g_probs[BB*HH*MM*MM];
__device__ __align__(16) float g_tpad[NROWS*KPAD];
__device__ __align__(16) float g_w2pad[NE*KPAD];
__device__ __align__(16) float g_dl[BB*LL];
__device__ __align__(16) float g_split[2*NROWS*DFF/2]; // split-K partials (2 x 2048*768 fits: 2*1.57M floats)

// ---------------- block reduction helper ----------------
__device__ __forceinline__ float block_reduce_sum(float v) {
    __shared__ float red[8];
    int lane = threadIdx.x & 31, wid = threadIdx.x >> 5, nw = (int)(blockDim.x >> 5);
    #pragma unroll
    for (int o = 16; o > 0; o >>= 1) v += __shfl_down_sync(0xffffffffu, v, o);
    __syncthreads();
    if (lane == 0) red[wid] = v;
    __syncthreads();
    float s = 0.f;
    for (int i = 0; i < nw; i++) s += red[i];
    return s;
}

// ---------------- mention pooling ----------------
__global__ void dot_kernel(const float* __restrict__ lhs, const float* __restrict__ aw,
                           float* __restrict__ dl) {
    int bl = blockIdx.x;                 // b*32 + l
    int b = bl >> 5, l = bl & 31;
    const float* r = lhs + ((size_t)b*SS + l)*DD;
    float s = 0.f;
    for (int d = threadIdx.x; d < DD; d += blockDim.x) s += r[d]*aw[d];
    s = block_reduce_sum(s);
    if (threadIdx.x == 0) dl[bl] = s;
}

// pos/mask are int32 (jax x64 disabled silently downcasts the int64 cast).
__global__ void pool_kernel(const float* __restrict__ lhs,
                            const int* __restrict__ pos,
                            const int* __restrict__ mask,
                            const float* __restrict__ dl,
                            const float* __restrict__ attn_b,
                            float* __restrict__ x) {
    int bm = blockIdx.x;                 // b*128 + m
    int b = bm >> 7;
    __shared__ float p[LL];
    __shared__ int s_vlen;
    if (threadIdx.x == 0) {
        int vlen = 0;
        if (mask[bm] != 0) {
            const int* pr = pos + (size_t)bm*LL;
            while (vlen < LL && pr[vlen] != -1) vlen++;
        }
        s_vlen = vlen;
        float ab = attn_b[0];
        float lg[LL];
        float mx = -INFINITY;
        for (int l = 0; l < LL; l++) {
            lg[l] = (l < vlen ? dl[b*LL + l] : 0.f) + ab;
            mx = fmaxf(mx, lg[l]);
        }
        float sum = 0.f;
        for (int l = 0; l < LL; l++) { float e = expf(lg[l]-mx); p[l] = e; sum += e; }
        float inv = 1.f/sum;
        for (int l = 0; l < LL; l++) p[l] *= inv;
    }
    __syncthreads();
    int vlen = s_vlen;
    float* xr = x + (size_t)bm*DD;
    for (int d = threadIdx.x; d < DD; d += blockDim.x) {
        float acc = 0.f;
        for (int l = 0; l < vlen; l++)
            acc += p[l] * lhs[((size_t)b*SS + l)*DD + d];
        xr[d] = acc;
    }
}

// ---------------- shared tf32 helpers ----------------
__device__ __forceinline__ uint32_t f2tf32(float x) {
    uint32_t y;
    asm("cvt.rna.tf32.f32 %0, %1;" : "=r"(y) : "f"(x));
    return y;
}

__device__ __forceinline__ void mma_tf32(float* c, const uint32_t* a, const uint32_t* b) {
    asm volatile(
        "mma.sync.aligned.m16n8k8.row.col.f32.tf32.tf32.f32 "
        "{%0,%1,%2,%3}, {%4,%5,%6,%7}, {%8,%9}, {%0,%1,%2,%3};\n"
        : "+f"(c[0]), "+f"(c[1]), "+f"(c[2]), "+f"(c[3])
        : "r"(a[0]), "r"(a[1]), "r"(a[2]), "r"(a[3]), "r"(b[0]), "r"(b[1]));
}

__device__ __forceinline__ uint32_t smem_u32p(const void* p) {
    uint32_t a;
    asm("{ .reg .u64 t; cvta.to.shared.u64 t, %1; cvt.u32.u64 %0, t; }" : "=r"(a) : "l"(p));
    return a;
}

__device__ __forceinline__ void cpa16(uint32_t dst, const void* src, int sz) {
    asm volatile("cp.async.cg.shared.global [%0], [%1], 16, %2;"
                 :: "r"(dst), "l"(src), "r"(sz) : "memory");
}
__device__ __forceinline__ void cpa_commit() {
    asm volatile("cp.async.commit_group;" ::: "memory");
}

#define SMS 136   // 128 + 8 pad; conflict-free

// ============ tgemm_big: 256x128 tile, cp.async 3-stage, fp32 smem [row][k20] ============
// C[M,N] = A[M,K]*B[N,K]^T (+bias)(+relu). M mult of 256, K mult of 32.
// 256 threads = 8 warps (4m x 2n), warp tile 64x64. tf32 cvt at fragment load.
#define RSTR 20                     // row stride in words (16 k + 4 pad); bank-perm
#define STG_W ((256+128)*RSTR)      // words per stage
#define BIG_SMEM (3*STG_W*4)        // 92160 bytes

__global__ __launch_bounds__(256)
void tgemm_big(const float* __restrict__ A, const float* __restrict__ B,
               const float* __restrict__ bias, float* __restrict__ C,
               int M, int N, int K, int lda, int ldb, int ldc, int relu) {
    extern __shared__ float sm[];
    uint32_t sb = smem_u32p(sm);
    int t = threadIdx.x;
    int m0 = blockIdx.y * 256;
    int n0 = blockIdx.x * 128;

    const float* Ap = A + (size_t)(m0 + t)*lda;      // A: thread owns row t
    int brow = t >> 1, bko = (t & 1)*8;              // B: row t>>1, k-half
    int bsz = ((n0 + brow) < N) ? 16 : 0;            // zero-fill invalid B rows
    const float* Bp = B + (size_t)(n0 + brow)*ldb + bko;

    int warp = t >> 5, lane = t & 31;
    int group = lane >> 2, tg = lane & 3;
    int wm = (warp >> 1) * 64;
    int wn = (warp & 1) * 64;

    float acc[4][8][4];
    #pragma unroll
    for (int mi = 0; mi < 4; mi++)
        #pragma unroll
        for (int ni = 0; ni < 8; ni++)
            #pragma unroll
            for (int r = 0; r < 4; r++) acc[mi][ni][r] = 0.f;

    // byte addresses of this thread's staging slots (per stage s)
    uint32_t a_dst0 = sb + t*(RSTR*4);
    uint32_t b_dst0 = sb + (256*RSTR + brow*RSTR + bko)*4;

    int NT = K >> 4;

    // prologue: stages 0 and 1
    #pragma unroll
    for (int s = 0; s < 2; s++) {
        uint32_t ad = a_dst0 + s*(STG_W*4);
        uint32_t bd = b_dst0 + s*(STG_W*4);
        const float* ag = Ap + s*16;
        const float* bg = Bp + s*16;
        cpa16(ad,      ag,      16); cpa16(ad + 16, ag + 4,  16);
        cpa16(ad + 32, ag + 8,  16); cpa16(ad + 48, ag + 12, 16);
        cpa16(bd, bg, bsz); cpa16(bd + 16, bg + 4, bsz);
        cpa_commit();
    }

    int s = 0;
    for (int kt = 0; kt < NT; kt++) {
        if (kt == NT - 1) asm volatile("cp.async.wait_group 0;" ::: "memory");
        else              asm volatile("cp.async.wait_group 1;" ::: "memory");
        __syncthreads();

        // issue stage kt+2
        if (kt + 2 < NT) {
            int sn = (kt + 2) % 3;
            uint32_t ad = a_dst0 + sn*(STG_W*4);
            uint32_t bd = b_dst0 + sn*(STG_W*4);
            const float* ag = Ap + (kt + 2)*16;
            const float* bg = Bp + (kt + 2)*16;
            cpa16(ad,      ag,      16); cpa16(ad + 16, ag + 4,  16);
            cpa16(ad + 32, ag + 8,  16); cpa16(ad + 48, ag + 12, 16);
            cpa16(bd, bg, bsz); cpa16(bd + 16, bg + 4, bsz);
            cpa_commit();
        }

        const float* Asf = sm + s*STG_W;
        const float* Bsf = Asf + 256*RSTR;
        #pragma unroll
        for (int kk = 0; kk < 16; kk += 8) {
            uint32_t af[4][4], bf[8][2];
            #pragma unroll
            for (int mi = 0; mi < 4; mi++) {
                int ar = wm + mi*16 + group;
                af[mi][0] = f2tf32(Asf[ar*RSTR + kk + tg]);
                af[mi][1] = f2tf32(Asf[(ar+8)*RSTR + kk + tg]);
                af[mi][2] = f2tf32(Asf[ar*RSTR + kk + tg + 4]);
                af[mi][3] = f2tf32(Asf[(ar+8)*RSTR + kk + tg + 4]);
            }
            #pragma unroll
            for (int ni = 0; ni < 8; ni++) {
                int bc = wn + ni*8 + group;
                bf[ni][0] = f2tf32(Bsf[bc*RSTR + kk + tg]);
                bf[ni][1] = f2tf32(Bsf[bc*RSTR + kk + tg + 4]);
            }
            #pragma unroll
            for (int mi = 0; mi < 4; mi++)
                #pragma unroll
                for (int ni = 0; ni < 8; ni++)
                    mma_tf32(acc[mi][ni], af[mi], bf[ni]);
        }
        s = (s + 1) % 3;
    }

    // epilogue
    #pragma unroll
    for (int mi = 0; mi < 4; mi++) {
        int gr0 = m0 + wm + mi*16 + group;
        #pragma unroll
        for (int ni = 0; ni < 8; ni++) {
            int gc = n0 + wn + ni*8 + tg*2;
            #pragma unroll
            for (int half = 0; half < 2; half++) {
                int gm = gr0 + half*8;
                if (gc + 1 < N) {
                    float v0 = acc[mi][ni][half*2+0] + (bias ? bias[gc]   : 0.f);
                    float v1 = acc[mi][ni][half*2+1] + (bias ? bias[gc+1] : 0.f);
                    if (relu) { v0 = fmaxf(v0, 0.f); v1 = fmaxf(v1, 0.f); }
                    *(float2*)&C[(size_t)gm*ldc + gc] = make_float2(v0, v1);
                } else {
                    #pragma unroll
                    for (int j = 0; j < 2; j++) {
                        int gn = gc + j;
                        if (gn < N) {
                            float v = acc[mi][ni][half*2 + j] + (bias ? bias[gn] : 0.f);
                            if (relu) v = fmaxf(v, 0.f);
                            C[(size_t)gm*ldc + gn] = v;
                        }
                    }
                }
            }
        }
    }
}

// ============ tgemm_nt: 128x128 tile, 8 warps (2m x 4n), warp 64x32, split-K via z ============
__global__ __launch_bounds__(256, 2)
void tgemm_nt(const float* __restrict__ A, const float* __restrict__ B,
              const float* __restrict__ bias, float* __restrict__ C,
              int M, int N, int K, int lda, int ldb, int ldc, int Npad, int relu,
              int kz, size_t cz) {
    A += (size_t)blockIdx.z * kz;
    B += (size_t)blockIdx.z * kz;
    C += (size_t)blockIdx.z * cz;

    __shared__ uint32_t As[2][16][SMS];
    __shared__ uint32_t Bs[2][16][SMS];
    int t = threadIdx.x;
    int m0 = blockIdx.y * 128;
    int n0 = blockIdx.x * 128;

    int lr = t & 127;
    int lk = (t >> 7) * 8;
    const float* Aptr = A + (size_t)(m0 + lr)*lda + lk;
    bool bv = (n0 + lr) < N;
    const float* Bptr = B + (size_t)(n0 + lr)*ldb + lk;

    int warp  = t >> 5, lane = t & 31;
    int group = lane >> 2, tg = lane & 3;
    int wm = (warp >> 2) * 64;
    int wn = (warp & 3) * 32;

    float acc[4][4][4];
    #pragma unroll
    for (int mi = 0; mi < 4; mi++)
        #pragma unroll
        for (int ni = 0; ni < 4; ni++)
            #pragma unroll
            for (int r = 0; r < 4; r++) acc[mi][ni][r] = 0.f;

    float4 pa0 = *(const float4*)(Aptr + 0);
    float4 pa1 = *(const float4*)(Aptr + 4);
    float4 pb0 = bv ? *(const float4*)(Bptr + 0) : make_float4(0.f,0.f,0.f,0.f);
    float4 pb1 = bv ? *(const float4*)(Bptr + 4) : make_float4(0.f,0.f,0.f,0.f);
    As[0][lk+0][lr] = f2tf32(pa0.x); As[0][lk+1][lr] = f2tf32(pa0.y);
    As[0][lk+2][lr] = f2tf32(pa0.z); As[0][lk+3][lr] = f2tf32(pa0.w);
    As[0][lk+4][lr] = f2tf32(pa1.x); As[0][lk+5][lr] = f2tf32(pa1.y);
    As[0][lk+6][lr] = f2tf32(pa1.z); As[0][lk+7][lr] = f2tf32(pa1.w);
    Bs[0][lk+0][lr] = f2tf32(pb0.x); Bs[0][lk+1][lr] = f2tf32(pb0.y);
    Bs[0][lk+2][lr] = f2tf32(pb0.z); Bs[0][lk+3][lr] = f2tf32(pb0.w);
    Bs[0][lk+4][lr] = f2tf32(pb1.x); Bs[0][lk+5][lr] = f2tf32(pb1.y);
    Bs[0][lk+6][lr] = f2tf32(pb1.z); Bs[0][lk+7][lr] = f2tf32(pb1.w);
    __syncthreads();

    int cur = 0;
    for (int k0 = 16; k0 <= K; k0 += 16) {
        bool more = (k0 < K);
        if (more) {
            pa0 = *(const float4*)(Aptr + k0);
            pa1 = *(const float4*)(Aptr + k0 + 4);
            if (bv) {
                pb0 = *(const float4*)(Bptr + k0);
                pb1 = *(const float4*)(Bptr + k0 + 4);
            }
        }

        #pragma unroll
        for (int kk = 0; kk < 16; kk += 8) {
            uint32_t af[4][4], bf[4][2];
            #pragma unroll
            for (int mi = 0; mi < 4; mi++) {
                int ar = wm + mi*16 + group;
                af[mi][0] = As[cur][kk+tg  ][ar];
                af[mi][1] = As[cur][kk+tg  ][ar+8];
                af[mi][2] = As[cur][kk+tg+4][ar];
                af[mi][3] = As[cur][kk+tg+4][ar+8];
            }
            #pragma unroll
            for (int ni = 0; ni < 4; ni++) {
                int bc = wn + ni*8 + group;
                bf[ni][0] = Bs[cur][kk+tg  ][bc];
                bf[ni][1] = Bs[cur][kk+tg+4][bc];
            }
            #pragma unroll
            for (int mi = 0; mi < 4; mi++)
                #pragma unroll
                for (int ni = 0; ni < 4; ni++)
                    mma_tf32(acc[mi][ni], af[mi], bf[ni]);
        }

        if (more) {
            int nxt = cur ^ 1;
            As[nxt][lk+0][lr] = f2tf32(pa0.x); As[nxt][lk+1][lr] = f2tf32(pa0.y);
            As[nxt][lk+2][lr] = f2tf32(pa0.z); As[nxt][lk+3][lr] = f2tf32(pa0.w);
            As[nxt][lk+4][lr] = f2tf32(pa1.x); As[nxt][lk+5][lr] = f2tf32(pa1.y);
            As[nxt][lk+6][lr] = f2tf32(pa1.z); As[nxt][lk+7][lr] = f2tf32(pa1.w);
            Bs[nxt][lk+0][lr] = f2tf32(pb0.x); Bs[nxt][lk+1][lr] = f2tf32(pb0.y);
            Bs[nxt][lk+2][lr] = f2tf32(pb0.z); Bs[nxt][lk+3][lr] = f2tf32(pb0.w);
            Bs[nxt][lk+4][lr] = f2tf32(pb1.x); Bs[nxt][lk+5][lr] = f2tf32(pb1.y);
            Bs[nxt][lk+6][lr] = f2tf32(pb1.z); Bs[nxt][lk+7][lr] = f2tf32(pb1.w);
            __syncthreads();
            cur = nxt;
        }
    }

    #pragma unroll
    for (int mi = 0; mi < 4; mi++) {
        int gr0 = m0 + wm + mi*16 + group;
        #pragma unroll
        for (int ni = 0; ni < 4; ni++) {
            int gc = n0 + wn + ni*8 + tg*2;
            #pragma unroll
            for (int half = 0; half < 2; half++) {
                int gm = gr0 + half*8;
                if (gc + 1 < N) {
                    float v0 = acc[mi][ni][half*2+0] + (bias ? bias[gc]   : 0.f);
                    float v1 = acc[mi][ni][half*2+1] + (bias ? bias[gc+1] : 0.f);
                    if (relu) { v0 = fmaxf(v0, 0.f); v1 = fmaxf(v1, 0.f); }
                    *(float2*)&C[(size_t)gm*ldc + gc] = make_float2(v0, v1);
                } else {
                    #pragma unroll
                    for (int j = 0; j < 2; j++) {
                        int gn = gc + j;
                        if (gn < Npad) {
                            float v = 0.f;
                            if (gn < N) {
                                v = acc[mi][ni][half*2 + j] + (bias ? bias[gn] : 0.f);
                                if (relu) v = fmaxf(v, 0.f);
                            }
                            C[(size_t)gm*ldc + gn] = v;
                        }
                    }
                }
            }
        }
    }
}

// ---------------- split-K reduction: dst = p0 + p1 + bias ----------------
__global__ void reduce_split(const float* __restrict__ parts, size_t zstride,
                             const float* __restrict__ bias, int cols,
                             float* __restrict__ dst, size_t total) {
    size_t i = (size_t)blockIdx.x*blockDim.x + threadIdx.x;
    if (i < total) {
        float s = parts[i] + parts[zstride + i];
        if (bias) s += bias[i % cols];
        dst[i] = s;
    }
}

// ---------------- attention (one block per (b,h), 128 threads = 128 queries) ----------------
__global__ __launch_bounds__(128)
void attn_kernel(const float* __restrict__ qkv, float* __restrict__ probs,
                 float* __restrict__ attnout) {
    __shared__ float Ks[128][64];
    int bh = blockIdx.x;
    int b = bh / HH, h = bh % HH;
    int t = threadIdx.x;
    const float* base = qkv + (size_t)b*MM*(3*DD);
    for (int idx = t; idx < 128*64; idx += 128) {
        int j = idx >> 6, d = idx & 63;
        Ks[j][d] = base[(size_t)j*(3*DD) + DD + h*HD + d];
    }
    __syncthreads();
    float q[64];
    const float* qrow = base + (size_t)t*(3*DD) + h*HD;
    #pragma unroll
    for (int d0 = 0; d0 < 64; d0 += 4) {
        float4 v = *(const float4*)(qrow + d0);
        q[d0] = v.x; q[d0+1] = v.y; q[d0+2] = v.z; q[d0+3] = v.w;
    }
    float mx = -INFINITY;
    float* prow = probs + (size_t)bh*MM*MM;
    const float scale = 0.125f;
    for (int j = 0; j < 128; j++) {
        float s = 0.f;
        #pragma unroll
        for (int d = 0; d < 64; d++) s += q[d]*Ks[j][d];
        s *= scale;
        mx = fmaxf(mx, s);
        prow[(size_t)j*128 + t] = s;
    }
    __syncthreads();
    for (int idx = t; idx < 128*64; idx += 128) {
        int j = idx >> 6, d = idx & 63;
        Ks[j][d] = base[(size_t)j*(3*DD) + 2*DD + h*HD + d];
    }
    __syncthreads();
    float acc[64];
    #pragma unroll
    for (int d = 0; d < 64; d++) acc[d] = 0.f;
    float sum = 0.f;
    for (int j = 0; j < 128; j++) {
        float p = expf(prow[(size_t)j*128 + t] - mx);
        sum += p;
        #pragma unroll
        for (int d = 0; d < 64; d++) acc[d] += p*Ks[j][d];
    }
    float inv = 1.f/sum;
    float* orow = attnout + (size_t)(b*MM + t)*DD + h*HD;
    #pragma unroll
    for (int d = 0; d < 64; d++) orow[d] = acc[d]*inv;
}

// ---------------- fused residual + layernorm (in-place into x) ----------------
__global__ void add_ln_kernel(float* __restrict__ x, const float* __restrict__ y,
                              const float* __restrict__ w, const float* __restrict__ b) {
    __shared__ float buf[DD];
    int row = blockIdx.x, t = threadIdx.x;
    float* xr = x + (size_t)row*DD;
    const float* yr = y + (size_t)row*DD;
    float ls = 0.f;
    for (int d = t; d < DD; d += blockDim.x) {
        float v = xr[d] + yr[d];
        buf[d] = v;
        ls += v;
    }
    float mean = block_reduce_sum(ls) * (1.f/DD);
    float lv = 0.f;
    for (int d = t; d < DD; d += blockDim.x) {
        float c = buf[d] - mean;
        lv += c*c;
    }
    float var = block_reduce_sum(lv) * (1.f/DD);
    float r = rsqrtf(var + 1e-5f);
    for (int d = t; d < DD; d += blockDim.x)
        xr[d] = (buf[d] - mean)*r*w[d] + b[d];
}

// ---------------- pad cls_w2 [NE,100] -> [NE,128] ----------------
__global__ void pad_w2_kernel(const float* __restrict__ w2, float* __restrict__ w2p) {
    size_t i = (size_t)blockIdx.x*blockDim.x + threadIdx.x;
    if (i < (size_t)NE*KPAD) {
        int r = (int)(i >> 7), c = (int)(i & 127);
        w2p[i] = (c < 100) ? w2[(size_t)r*100 + c] : 0.f;
    }
}

// ---------------- launch ----------------
extern "C" void kernel_launch(void* const* d_in, const int* in_sizes, int n_in,
                              void* d_out, int out_size) {
    (void)in_sizes; (void)n_in; (void)out_size;
    const float* lhs    = (const float*)d_in[0];
    const int*   pos    = (const int*)d_in[1];     // int32
    const int*   mask   = (const int*)d_in[2];     // int32
    const float* attn_w = (const float*)d_in[3];
    const float* attn_b = (const float*)d_in[4];
    const float* qkv_w  = (const float*)d_in[5];
    const float* qkv_b  = (const float*)d_in[6];
    const float* out_w  = (const float*)d_in[7];
    const float* out_b  = (const float*)d_in[8];
    const float* ln1_w  = (const float*)d_in[9];
    const float* ln1_b  = (const float*)d_in[10];
    const float* ff1_w  = (const float*)d_in[11];
    const float* ff1_b  = (const float*)d_in[12];
    const float* ff2_w  = (const float*)d_in[13];
    const float* ff2_b  = (const float*)d_in[14];
    const float* ln2_w  = (const float*)d_in[15];
    const float* ln2_b  = (const float*)d_in[16];
    const float* cls_w1 = (const float*)d_in[17];
    const float* cls_w2 = (const float*)d_in[18];
    const float* cls_b2 = (const float*)d_in[19];
    float* out = (float*)d_out;

    float *x, *qkv, *attnout, *branch, *ffh, *probs, *tpad, *w2pad, *dl, *split;
    cudaGetSymbolAddress((void**)&x,       g_x);
    cudaGetSymbolAddress((void**)&qkv,     g_qkv);
    cudaGetSymbolAddress((void**)&attnout, g_attnout);
    cudaGetSymbolAddress((void**)&branch,  g_branch);
    cudaGetSymbolAddress((void**)&ffh,     g_ffh);
    cudaGetSymbolAddress((void**)&probs,   g_probs);
    cudaGetSymbolAddress((void**)&tpad,    g_tpad);
    cudaGetSymbolAddress((void**)&w2pad,   g_w2pad);
    cudaGetSymbolAddress((void**)&dl,      g_dl);
    cudaGetSymbolAddress((void**)&split,   g_split);

    cudaFuncSetAttribute(tgemm_big, cudaFuncAttributeMaxDynamicSharedMemorySize, BIG_SMEM);

    const size_t XE = (size_t)NROWS*DD;   // 2048*768 elements

    pad_w2_kernel<<<(NE*KPAD + 255)/256, 256>>>(cls_w2, w2pad);

    dot_kernel<<<BB*LL, 128>>>(lhs, attn_w, dl);
    pool_kernel<<<NROWS, 256>>>(lhs, pos, mask, dl, attn_b, x);

    for (int i = 0; i < NL; i++) {
        tgemm_big<<<dim3(18,8), 256, BIG_SMEM>>>(x, qkv_w + (size_t)i*3*DD*DD,
                                                 qkv_b + (size_t)i*3*DD,
                                                 qkv, NROWS, 3*DD, DD, DD, DD, 3*DD, 0);
        attn_kernel<<<BB*HH, 128>>>(qkv, probs, attnout);
        // out-proj, split-K 2 (K=768 -> 2x384)
        tgemm_nt<<<dim3(6,16,2), 256>>>(attnout, out_w + (size_t)i*DD*DD, (const float*)nullptr,
                                        split, NROWS, DD, 384, DD, DD, DD, DD, 0, 384, XE);
        reduce_split<<<(int)((XE + 255)/256), 256>>>(split, XE, out_b + (size_t)i*DD, DD,
                                                     branch, XE);
        add_ln_kernel<<<NROWS, 256>>>(x, branch, ln1_w + (size_t)i*DD, ln1_b + (size_t)i*DD);
        tgemm_big<<<dim3(24,8), 256, BIG_SMEM>>>(x, ff1_w + (size_t)i*DFF*DD,
                                                 ff1_b + (size_t)i*DFF,
                                                 ffh, NROWS, DFF, DD, DD, DD, DFF, 1);
        // ff2, split-K 2 (K=3072 -> 2x1536)
        tgemm_nt<<<dim3(6,16,2), 256>>>(ffh, ff2_w + (size_t)i*DD*DFF, (const float*)nullptr,
                                        split, NROWS, DD, 1536, DFF, DFF, DD, DD, 0, 1536, XE);
        reduce_split<<<(int)((XE + 255)/256), 256>>>(split, XE, ff2_b + (size_t)i*DD, DD,
                                                     branch, XE);
        add_ln_kernel<<<NROWS, 256>>>(x, branch, ln2_w + (size_t)i*DD, ln2_b + (size_t)i*DD);
    }

    tgemm_nt<<<dim3(1,16,1), 256>>>(x, cls_w1, (const float*)nullptr, tpad,
                                    NROWS, 100, DD, DD, DD, KPAD, KPAD, 0, 0, 0);
    tgemm_big<<<dim3((NE + 127)/128, 8), 256, BIG_SMEM>>>(tpad, w2pad, cls_b2, out,
                                                          NROWS, NE, KPAD, KPAD, KPAD, NE, 0);
}